// round 8
// baseline (speedup 1.0000x reference)
#include <cuda_runtime.h>
#include <cstddef>
#include <cstdint>

// Problem constants (match reference)
#define BB  4
#define SS  1024
#define DD  1024
#define HH  16
#define DKV 64          // DK == DV == 64
#define NR  65          // 2*MAX_REL+1 relative buckets

// ---------------------------------------------------------------------------
// Scratch (static device globals; runtime allocation is forbidden)
// ---------------------------------------------------------------------------
__device__ float g_Q  [(size_t)BB * SS * DD];        // [B,S,H*DK]  projected q
__device__ float g_K  [(size_t)BB * SS * DD];        // [B,S,H*DK]  projected k
__device__ float g_V  [(size_t)BB * SS * DD];        // [B,S,H*DV]  projected v
__device__ float g_CTX[(size_t)BB * SS * DD];        // [B,S,H*DV]  context
__device__ float g_QE [(size_t)BB * HH * SS * NR];   // [BH,S,65]   q . emb_k[r]
__device__ float g_AW [(size_t)BB * HH * SS * NR];   // [BH,S,65]   bucket-summed attn

// ---------------------------------------------------------------------------
// Generic SGEMM + bias: C[M,N] = A[M,K] @ W[K,N] + bias[N]
// 64x64 block tile, BK=16, 256 threads, 4x4 register tile per thread.
// Requires M%64==0, N%64==0, K%16==0 (true for all uses here).
// ---------------------------------------------------------------------------
__global__ __launch_bounds__(256) void gemm_bias_kernel(
    const float* __restrict__ A, const float* __restrict__ W,
    const float* __restrict__ bias, float* __restrict__ C,
    int M, int N, int K)
{
    __shared__ float As[16][65];   // [k][m], padded (conflict-free stores)
    __shared__ float Ws[16][64];   // [k][n]
    const int tid = threadIdx.x;
    const int tx = tid & 15, ty = tid >> 4;
    const int row0 = blockIdx.y * 64;
    const int col0 = blockIdx.x * 64;

    float acc[4][4] = {};

    for (int k0 = 0; k0 < K; k0 += 16) {
#pragma unroll
        for (int i = 0; i < 4; i++) {
            int idx = tid + i * 256;          // 1024 elems
            int r = idx >> 4, c = idx & 15;
            As[c][r] = A[(size_t)(row0 + r) * K + (k0 + c)];
        }
#pragma unroll
        for (int i = 0; i < 4; i++) {
            int idx = tid + i * 256;
            int r = idx >> 6, c = idx & 63;
            Ws[r][c] = W[(size_t)(k0 + r) * N + (col0 + c)];
        }
        __syncthreads();
#pragma unroll
        for (int kk = 0; kk < 16; kk++) {
            float a[4], w[4];
#pragma unroll
            for (int i = 0; i < 4; i++) a[i] = As[kk][ty * 4 + i];
#pragma unroll
            for (int j = 0; j < 4; j++) w[j] = Ws[kk][tx * 4 + j];
#pragma unroll
            for (int i = 0; i < 4; i++)
#pragma unroll
                for (int j = 0; j < 4; j++)
                    acc[i][j] = fmaf(a[i], w[j], acc[i][j]);
        }
        __syncthreads();
    }

#pragma unroll
    for (int i = 0; i < 4; i++) {
        int r = row0 + ty * 4 + i;
#pragma unroll
        for (int j = 0; j < 4; j++) {
            int c = col0 + tx * 4 + j;
            C[(size_t)r * N + c] = acc[i][j] + bias[c];
        }
    }
}

// ---------------------------------------------------------------------------
// qe[bh,q,r] = sum_d Q[b,q,h*64+d] * emb_k[r,d]   (unscaled; 1/8 applied later)
// One block handles 16 consecutive global rows g = bh*S + q (never straddles bh).
// ---------------------------------------------------------------------------
__global__ __launch_bounds__(256) void qe_kernel(const float* __restrict__ emb_k)
{
    __shared__ float E [NR][65];   // emb_k, padded rows
    __shared__ float Qs[16][64];
    const int tid = threadIdx.x;
    const int g0  = blockIdx.x * 16;
    const int bh  = g0 / SS;
    const int qb  = g0 % SS;
    const int b   = bh / HH, h = bh % HH;

    for (int idx = tid; idx < NR * 64; idx += 256) {
        int r = idx >> 6, d = idx & 63;
        E[r][d] = emb_k[idx];
    }
    for (int idx = tid; idx < 16 * 64; idx += 256) {
        int r = idx >> 6, d = idx & 63;
        Qs[r][d] = g_Q[(size_t)(b * SS + qb + r) * DD + h * DKV + d];
    }
    __syncthreads();

    for (int o = tid; o < 16 * NR; o += 256) {
        int row = o / NR, r = o % NR;
        float s = 0.f;
#pragma unroll
        for (int d = 0; d < 64; d++)
            s = fmaf(Qs[row][d], E[r][d], s);
        g_QE[(size_t)(g0 + row) * NR + r] = s;
    }
}

// ---------------------------------------------------------------------------
// scores[bh,q,k] = 0.125 * ( Q[q,:].K[k,:] + qe[q, clip(k-q,-32,32)+32] )
// grid (S/64, S/64, B*H). Writes raw scores into the attn output region
// (softmax kernel normalizes in-place).
// ---------------------------------------------------------------------------
__global__ __launch_bounds__(256) void scores_kernel(float* __restrict__ attn)
{
    __shared__ float Qs[64][65];   // [d][q] transposed, padded
    __shared__ float Ks[64][65];   // [d][k]
    const int tid = threadIdx.x;
    const int tx = tid & 15, ty = tid >> 4;
    const int bh = blockIdx.z;
    const int b  = bh / HH, h = bh % HH;
    const int q0 = blockIdx.y * 64;
    const int k0 = blockIdx.x * 64;

#pragma unroll
    for (int i = 0; i < 16; i++) {
        int idx = tid + i * 256;          // 4096 elems
        int r = idx >> 6, d = idx & 63;
        Qs[d][r] = g_Q[(size_t)(b * SS + q0 + r) * DD + h * DKV + d];
        Ks[d][r] = g_K[(size_t)(b * SS + k0 + r) * DD + h * DKV + d];
    }
    __syncthreads();

    float acc[4][4] = {};
#pragma unroll 16
    for (int d = 0; d < 64; d++) {
        float a[4], w[4];
#pragma unroll
        for (int i = 0; i < 4; i++) a[i] = Qs[d][ty * 4 + i];
#pragma unroll
        for (int j = 0; j < 4; j++) w[j] = Ks[d][tx * 4 + j];
#pragma unroll
        for (int i = 0; i < 4; i++)
#pragma unroll
            for (int j = 0; j < 4; j++)
                acc[i][j] = fmaf(a[i], w[j], acc[i][j]);
    }

#pragma unroll
    for (int i = 0; i < 4; i++) {
        int q = q0 + ty * 4 + i;
        const float* qe_row = &g_QE[(size_t)(bh * SS + q) * NR];
#pragma unroll
        for (int j = 0; j < 4; j++) {
            int k = k0 + tx * 4 + j;
            int rel = k - q;
            rel = (rel < -32) ? -32 : (rel > 32 ? 32 : rel);
            float s = 0.125f * (acc[i][j] + qe_row[rel + 32]);
            attn[((size_t)bh * SS + q) * SS + k] = s;
        }
    }
}

// ---------------------------------------------------------------------------
// FMA-pipe exp (avoids the MUFU throughput wall: 67M exps at rt 8/SMSP would
// cost ~0.5 ms). Degree-7 Taylor of 2^f on [0,1), rel err ~1.3e-6.
// Valid for x <= 0 (softmax shifted inputs); clamped at -87 (hard underflow).
// ---------------------------------------------------------------------------
__device__ __forceinline__ float fast_exp_neg(float x)
{
    x = fmaxf(x, -87.0f);
    float y = x * 1.4426950408889634f;   // log2(e)
    float n = floorf(y);
    float f = y - n;                     // [0,1)
    float p = 1.5252734e-5f;
    p = fmaf(p, f, 1.5403530e-4f);
    p = fmaf(p, f, 1.3333558e-3f);
    p = fmaf(p, f, 9.6181291e-3f);
    p = fmaf(p, f, 5.5504109e-2f);
    p = fmaf(p, f, 2.4022651e-1f);
    p = fmaf(p, f, 6.9314718e-1f);
    p = fmaf(p, f, 1.0f);
    int e = (int)n;                      // >= -126 after clamp
    float sc = __int_as_float((e + 127) << 23);
    return p * sc;
}

// ---------------------------------------------------------------------------
// Row softmax in-place + relative-bucket accumulation.
// One block (256 thr) per row g = bh*S + q. Buckets 1..63 have a unique k
// writer; buckets 0 (k-q<=-32) and 64 (k-q>=32) are block-reduced.
// ---------------------------------------------------------------------------
__global__ __launch_bounds__(256) void softmax_aw_kernel(float* __restrict__ attn)
{
    const size_t g = blockIdx.x;
    const int q   = (int)(g & (SS - 1));
    const int tid = threadIdx.x;
    float* row = attn + g * SS;

    __shared__ float red[256];
    __shared__ float aw_s[NR];

    float v[4];
    float m = -1e30f;
#pragma unroll
    for (int i = 0; i < 4; i++) {
        v[i] = row[tid + i * 256];
        m = fmaxf(m, v[i]);
    }
    red[tid] = m; __syncthreads();
    for (int s = 128; s > 0; s >>= 1) {
        if (tid < s) red[tid] = fmaxf(red[tid], red[tid + s]);
        __syncthreads();
    }
    m = red[0]; __syncthreads();

    float sum = 0.f;
#pragma unroll
    for (int i = 0; i < 4; i++) {
        v[i] = fast_exp_neg(v[i] - m);
        sum += v[i];
    }
    red[tid] = sum; __syncthreads();
    for (int s = 128; s > 0; s >>= 1) {
        if (tid < s) red[tid] += red[tid + s];
        __syncthreads();
    }
    const float inv = 1.0f / red[0];
    __syncthreads();

    if (tid < NR) aw_s[tid] = 0.f;
    __syncthreads();

    float l0 = 0.f, l64 = 0.f;
#pragma unroll
    for (int i = 0; i < 4; i++) {
        int k = tid + i * 256;
        float p = v[i] * inv;
        row[k] = p;
        int dlt = k - q;
        if (dlt <= -32)      l0  += p;
        else if (dlt >= 32)  l64 += p;
        else                 aw_s[dlt + 32] = p;   // unique writer
    }

    red[tid] = l0; __syncthreads();
    for (int s = 128; s > 0; s >>= 1) {
        if (tid < s) red[tid] += red[tid + s];
        __syncthreads();
    }
    float t0 = red[0]; __syncthreads();

    red[tid] = l64; __syncthreads();
    for (int s = 128; s > 0; s >>= 1) {
        if (tid < s) red[tid] += red[tid + s];
        __syncthreads();
    }
    float t64 = red[0]; __syncthreads();

    if (tid == 0) { aw_s[0] += t0; aw_s[NR - 1] += t64; }
    __syncthreads();

    if (tid < NR) g_AW[g * NR + tid] = aw_s[tid];
}

// ---------------------------------------------------------------------------
// ctx[b,q,h*64+d] = attn[bh,q,:] @ V[b,:,h*64+d]  +  aw[bh,q,:] @ emb_v[:,d]
// grid (S/64, B*H); 64(q) x 64(d) tile, K=S mainloop + K'=65 relative tail.
// ---------------------------------------------------------------------------
__global__ __launch_bounds__(256) void ctx_kernel(const float* __restrict__ attn,
                                                  const float* __restrict__ emb_v)
{
    __shared__ float At[16][65];   // [k][q], padded
    __shared__ float Vs[16][64];   // [k][d]
    __shared__ float Aw[64][66];   // [q][r], padded
    __shared__ float Ev[NR][65];   // [r][d], padded
    const int tid = threadIdx.x;
    const int tx = tid & 15, ty = tid >> 4;
    const int bh = blockIdx.y;
    const int b  = bh / HH, h = bh % HH;
    const int q0 = blockIdx.x * 64;

    float acc[4][4] = {};

    for (int k0 = 0; k0 < SS; k0 += 16) {
#pragma unroll
        for (int i = 0; i < 4; i++) {
            int idx = tid + i * 256;
            int r = idx >> 4, c = idx & 15;
            At[c][r] = attn[((size_t)bh * SS + q0 + r) * SS + (k0 + c)];
        }
#pragma unroll
        for (int i = 0; i < 4; i++) {
            int idx = tid + i * 256;
            int r = idx >> 6, c = idx & 63;
            Vs[r][c] = g_V[(size_t)(b * SS + k0 + r) * DD + h * DKV + c];
        }
        __syncthreads();
#pragma unroll
        for (int kk = 0; kk < 16; kk++) {
            float a[4], w[4];
#pragma unroll
            for (int i = 0; i < 4; i++) a[i] = At[kk][ty * 4 + i];
#pragma unroll
            for (int j = 0; j < 4; j++) w[j] = Vs[kk][tx * 4 + j];
#pragma unroll
            for (int i = 0; i < 4; i++)
#pragma unroll
                for (int j = 0; j < 4; j++)
                    acc[i][j] = fmaf(a[i], w[j], acc[i][j]);
        }
        __syncthreads();
    }

    // relative-value tail: acc += Aw[q,:] @ emb_v
    for (int idx = tid; idx < 64 * NR; idx += 256) {
        int r = idx / NR, rr = idx % NR;
        Aw[r][rr] = g_AW[((size_t)bh * SS + q0 + r) * NR + rr];
    }
    for (int idx = tid; idx < NR * 64; idx += 256) {
        int r = idx >> 6, c = idx & 63;
        Ev[r][c] = emb_v[idx];
    }
    __syncthreads();
#pragma unroll 13
    for (int rr = 0; rr < NR; rr++) {
        float a[4], w[4];
#pragma unroll
        for (int i = 0; i < 4; i++) a[i] = Aw[ty * 4 + i][rr];
#pragma unroll
        for (int j = 0; j < 4; j++) w[j] = Ev[rr][tx * 4 + j];
#pragma unroll
        for (int i = 0; i < 4; i++)
#pragma unroll
            for (int j = 0; j < 4; j++)
                acc[i][j] = fmaf(a[i], w[j], acc[i][j]);
    }

#pragma unroll
    for (int i = 0; i < 4; i++) {
        int q = q0 + ty * 4 + i;
#pragma unroll
        for (int j = 0; j < 4; j++) {
            int d = tx * 4 + j;
            g_CTX[(size_t)(b * SS + q) * DD + h * DKV + d] = acc[i][j];
        }
    }
}

// ---------------------------------------------------------------------------
// kernel_launch
// Inputs (metadata order): key, value, query, Wk, bk, Wq, bq, Wv, bv, Wo, bo,
//                          emb_k, emb_v        (all float32)
// Output: concat(final_output [B*S*D], attn [B*H*S*S]) float32
// ---------------------------------------------------------------------------
extern "C" void kernel_launch(void* const* d_in, const int* in_sizes, int n_in,
                              void* d_out, int out_size)
{
    (void)in_sizes; (void)n_in; (void)out_size;
    const float* key   = (const float*)d_in[0];
    const float* value = (const float*)d_in[1];
    const float* query = (const float*)d_in[2];
    const float* Wk    = (const float*)d_in[3];
    const float* bk    = (const float*)d_in[4];
    const float* Wq    = (const float*)d_in[5];
    const float* bq    = (const float*)d_in[6];
    const float* Wv    = (const float*)d_in[7];
    const float* bv    = (const float*)d_in[8];
    const float* Wo    = (const float*)d_in[9];
    const float* bo    = (const float*)d_in[10];
    const float* emb_k = (const float*)d_in[11];
    const float* emb_v = (const float*)d_in[12];

    float* out  = (float*)d_out;
    float* attn = out + (size_t)BB * SS * DD;   // outputs concatenated in return order

    float *pQ, *pK, *pV, *pCTX;
    cudaGetSymbolAddress((void**)&pQ,   g_Q);
    cudaGetSymbolAddress((void**)&pK,   g_K);
    cudaGetSymbolAddress((void**)&pV,   g_V);
    cudaGetSymbolAddress((void**)&pCTX, g_CTX);

    const int M = BB * SS;   // 4096
    dim3 thr(256);
    dim3 gGemm(DD / 64, M / 64);                 // (16, 64)

    // 1-3. projections
    gemm_bias_kernel<<<gGemm, thr>>>(query, Wq, bq, pQ, M, DD, DD);
    gemm_bias_kernel<<<gGemm, thr>>>(key,   Wk, bk, pK, M, DD, DD);
    gemm_bias_kernel<<<gGemm, thr>>>(value, Wv, bv, pV, M, DD, DD);

    // 4. relative-key projections qe
    qe_kernel<<<(BB * HH * SS) / 16, thr>>>(emb_k);

    // 5. raw scores -> attn region
    scores_kernel<<<dim3(SS / 64, SS / 64, BB * HH), thr>>>(attn);

    // 6. softmax in-place + relative bucket sums
    softmax_aw_kernel<<<BB * HH * SS, thr>>>(attn);

    // 7. context (attn @ V + aw @ emb_v)
    ctx_kernel<<<dim3(SS / 64, BB * HH), thr>>>(attn, emb_v);

    // 8. output projection
    gemm_bias_kernel<<<gGemm, thr>>>(pCTX, Wo, bo, out, M, DD, DD);
}